// round 1
// baseline (speedup 1.0000x reference)
#include <cuda_runtime.h>
#include <cuda_bf16.h>
#include <cstdint>

#define BATCH 256
#define N 64
#define DIM 768
#define CHUNK 64
#define NCHUNK (DIM / CHUNK)
#define BIGV 1e9f

// Per-batch partials: [sim_num, dis_num, sim_cnt, err_cnt]
__device__ float g_partials[BATCH * 4];

__global__ __launch_bounds__(256) void cluster_kernel(
    const float* __restrict__ q,
    const float* __restrict__ p,
    const int* __restrict__ labels_g)
{
    __shared__ float qs[DIM];                 // 3 KB
    __shared__ float S[N][CHUNK + 1];         // 16.6 KB (padded: 2-way max conflicts)
    __shared__ float D[N][N + 1];             // 16.6 KB
    __shared__ float sq[N];
    __shared__ int   lab_in[N];
    __shared__ int   lab_cl[N];
    __shared__ unsigned long long s_active;   // bitmask of active points
    __shared__ unsigned long long wmin[8];
    __shared__ int   s_a, s_b;
    __shared__ int   s_kmask;
    __shared__ float wred[8][4];

    const int tid = threadIdx.x;
    const int b   = blockIdx.x;
    const float* pb = p + (size_t)b * N * DIM;
    const float* qb = q + (size_t)b * DIM;

    // ---- load q (whole row), labels, init cluster state ----
    for (int k = tid; k < DIM; k += 256) qs[k] = qb[k];
    if (tid < N) { lab_in[tid] = labels_g[b * N + tid]; lab_cl[tid] = tid; }
    if (tid == 0) { s_kmask = 0; s_active = ~0ull; }
    __syncthreads();
    if (tid < N) atomicOr(&s_kmask, 1 << lab_in[tid]);

    // ---- Gram matrix G = S S^T with S = q ⊙ P, chunked over d ----
    const int ti = tid >> 4, tj = tid & 15;
    const int i0 = ti * 4, j0 = tj * 4;
    float acc[4][4];
    #pragma unroll
    for (int r = 0; r < 4; r++)
        #pragma unroll
        for (int c = 0; c < 4; c++) acc[r][c] = 0.f;

    for (int ch = 0; ch < NCHUNK; ch++) {
        __syncthreads();   // protect S from previous iteration's readers
        // load 64 x 64 scaled tile; coalesced float4 global reads
        for (int s = tid; s < N * (CHUNK / 4); s += 256) {
            int row = s >> 4;            // CHUNK/4 == 16
            int kv  = (s & 15) * 4;
            const float4 v = *reinterpret_cast<const float4*>(pb + row * DIM + ch * CHUNK + kv);
            int kb = ch * CHUNK + kv;
            S[row][kv + 0] = v.x * qs[kb + 0];
            S[row][kv + 1] = v.y * qs[kb + 1];
            S[row][kv + 2] = v.z * qs[kb + 2];
            S[row][kv + 3] = v.w * qs[kb + 3];
        }
        __syncthreads();
        #pragma unroll 8
        for (int kk = 0; kk < CHUNK; kk++) {
            float av[4], bv[4];
            #pragma unroll
            for (int r = 0; r < 4; r++) av[r] = S[i0 + r][kk];
            #pragma unroll
            for (int c = 0; c < 4; c++) bv[c] = S[j0 + c][kk];
            #pragma unroll
            for (int r = 0; r < 4; r++)
                #pragma unroll
                for (int c = 0; c < 4; c++)
                    acc[r][c] = fmaf(av[r], bv[c], acc[r][c]);
        }
    }

    __syncthreads();
    #pragma unroll
    for (int r = 0; r < 4; r++)
        #pragma unroll
        for (int c = 0; c < 4; c++)
            D[i0 + r][j0 + c] = acc[r][c];
    __syncthreads();
    if (tid < N) sq[tid] = D[tid][tid];
    __syncthreads();

    // ---- distances + similar/dissimilar sums ----
    float simN = 0.f, disN = 0.f, simC = 0.f;
    #pragma unroll
    for (int r = 0; r < 4; r++) {
        #pragma unroll
        for (int c = 0; c < 4; c++) {
            int i = i0 + r, j = j0 + c;
            float d2 = sq[i] + sq[j] - 2.f * acc[r][c];
            float dist = (d2 > 0.f) ? sqrtf(d2) : 0.f;
            D[i][j] = dist;
            if (lab_in[i] == lab_in[j]) { simN += dist; simC += 1.f; }
            else                        { disN += dist; }
        }
    }
    __syncthreads();
    if (tid < N) D[tid][tid] = BIGV;   // diagonal = BIG as in reference
    __syncthreads();

    const int kclusters = __popc(s_kmask);
    const int merges = N - kclusters;

    // ---- single-linkage agglomeration ----
    for (int m = 0; m < merges; m++) {
        unsigned long long am = s_active;
        // masked argmin, upper triangle only (equivalent to full-matrix
        // first-occurrence argmin under symmetry), tie-break = smaller flat idx
        unsigned long long best = 0xFFFFFFFFFFFFFFFFull;
        int e0 = tid * 16;
        #pragma unroll
        for (int t = 0; t < 16; t++) {
            int e = e0 + t;
            int i = e >> 6, j = e & 63;
            float v = BIGV;
            if (i < j && ((am >> i) & 1ull) && ((am >> j) & 1ull)) v = D[i][j];
            unsigned long long key =
                ((unsigned long long)__float_as_uint(v) << 32) | (unsigned)e;
            best = (best < key) ? best : key;
        }
        #pragma unroll
        for (int o = 16; o > 0; o >>= 1) {
            unsigned long long other = __shfl_down_sync(0xFFFFFFFFu, best, o);
            best = (best < other) ? best : other;
        }
        if ((tid & 31) == 0) wmin[tid >> 5] = best;
        __syncthreads();
        if (tid == 0) {
            unsigned long long bb = wmin[0];
            #pragma unroll
            for (int w = 1; w < 8; w++) bb = (bb < wmin[w]) ? bb : wmin[w];
            int e = (int)(bb & 0xFFFFFFFFull);
            int i = e >> 6, j = e & 63;
            s_a = (i < j) ? i : j;
            s_b = (i < j) ? j : i;
        }
        __syncthreads();
        const int a = s_a, bq = s_b;
        if (tid < N) {
            // newrow = min(row a, row b); set row a and column a (as reference)
            float mv = fminf(D[a][tid], D[bq][tid]);
            D[a][tid]  = mv;
            D[tid][a]  = mv;
            if (lab_cl[tid] == bq) lab_cl[tid] = a;
        }
        if (tid == 0) s_active = am & ~(1ull << bq);
        __syncthreads();
    }

    // ---- error count: |adj - true_adj| over all pairs ----
    float errC = 0.f;
    #pragma unroll
    for (int r = 0; r < 4; r++) {
        #pragma unroll
        for (int c = 0; c < 4; c++) {
            int i = i0 + r, j = j0 + c;
            bool adj = (lab_cl[i] == lab_cl[j]);
            bool tru = (lab_in[i] == lab_in[j]);
            if (adj != tru) errC += 1.f;
        }
    }

    // ---- block reduce 4 values, fixed-order ----
    float v0 = simN, v1 = disN, v2 = simC, v3 = errC;
    #pragma unroll
    for (int o = 16; o > 0; o >>= 1) {
        v0 += __shfl_down_sync(0xFFFFFFFFu, v0, o);
        v1 += __shfl_down_sync(0xFFFFFFFFu, v1, o);
        v2 += __shfl_down_sync(0xFFFFFFFFu, v2, o);
        v3 += __shfl_down_sync(0xFFFFFFFFu, v3, o);
    }
    if ((tid & 31) == 0) {
        int w = tid >> 5;
        wred[w][0] = v0; wred[w][1] = v1; wred[w][2] = v2; wred[w][3] = v3;
    }
    __syncthreads();
    if (tid == 0) {
        float a0 = 0.f, a1 = 0.f, a2 = 0.f, a3 = 0.f;
        #pragma unroll
        for (int w = 0; w < 8; w++) {
            a0 += wred[w][0]; a1 += wred[w][1]; a2 += wred[w][2]; a3 += wred[w][3];
        }
        g_partials[b * 4 + 0] = a0;
        g_partials[b * 4 + 1] = a1;
        g_partials[b * 4 + 2] = a2;
        g_partials[b * 4 + 3] = a3;
    }
}

__global__ __launch_bounds__(256) void finalize_kernel(float* __restrict__ out)
{
    __shared__ double sh[8][4];
    const int tid = threadIdx.x;   // 256 threads, one per batch
    double v0 = g_partials[tid * 4 + 0];
    double v1 = g_partials[tid * 4 + 1];
    double v2 = g_partials[tid * 4 + 2];
    double v3 = g_partials[tid * 4 + 3];
    #pragma unroll
    for (int o = 16; o > 0; o >>= 1) {
        v0 += __shfl_down_sync(0xFFFFFFFFu, v0, o);
        v1 += __shfl_down_sync(0xFFFFFFFFu, v1, o);
        v2 += __shfl_down_sync(0xFFFFFFFFu, v2, o);
        v3 += __shfl_down_sync(0xFFFFFFFFu, v3, o);
    }
    if ((tid & 31) == 0) {
        int w = tid >> 5;
        sh[w][0] = v0; sh[w][1] = v1; sh[w][2] = v2; sh[w][3] = v3;
    }
    __syncthreads();
    if (tid == 0) {
        double simN = 0.0, disN = 0.0, simC = 0.0, errC = 0.0;
        #pragma unroll
        for (int w = 0; w < 8; w++) {
            simN += sh[w][0]; disN += sh[w][1]; simC += sh[w][2]; errC += sh[w][3];
        }
        double disC = (double)BATCH * N * N - simC;
        double res = errC / (double)BATCH + 0.5 * (simN / simC - disN / disC);
        out[0] = (float)res;
    }
}

extern "C" void kernel_launch(void* const* d_in, const int* in_sizes, int n_in,
                              void* d_out, int out_size)
{
    const float* q   = (const float*)d_in[0];  // [256, 768]
    const float* p   = (const float*)d_in[1];  // [256, 64, 768]
    const int*   lab = (const int*)d_in[2];    // [256, 64]
    (void)in_sizes; (void)n_in; (void)out_size;

    cluster_kernel<<<BATCH, 256>>>(q, p, lab);
    finalize_kernel<<<1, 256>>>((float*)d_out);
}

// round 2
// speedup vs baseline: 1.4431x; 1.4431x over previous
#include <cuda_runtime.h>
#include <cstdint>

#define BATCH 256
#define N 64
#define DIM 768
#define CHUNK 64
#define NCHUNK 12
#define DP 68                      // D row pitch (floats): mult of 4 for float4
#define BIGV 1e9f
#define KINF 0xFFFFFFFFFFFFFFFFull

// Per-batch partials: [sim_num, dis_num, sim_cnt, err_cnt]
__device__ float g_partials[BATCH * 4];

__device__ __forceinline__ unsigned long long u64min(unsigned long long a, unsigned long long b) {
    return a < b ? a : b;
}
__device__ __forceinline__ unsigned long long packkey(float v, int flat) {
    return (((unsigned long long)__float_as_uint(v)) << 32) | (unsigned)flat;
}

union F4U { float4 f; unsigned long long u[2]; };

__global__ __launch_bounds__(128) void cluster_kernel(
    const float* __restrict__ q,
    const float* __restrict__ p,
    const int* __restrict__ labels_g)
{
    __shared__ float qs[DIM];                         // 3 KB
    __shared__ float ST[CHUNK][64];                   // 16 KB, k-major, 4-float-block XOR swizzle
    __shared__ float D[N][DP];                        // 17 KB
    __shared__ unsigned long long rowkey_sm[N];       // 512 B
    __shared__ float sqv[N];
    __shared__ int   lab_in[N];
    __shared__ int   lab_sh[N];
    __shared__ int   s_kmask;
    __shared__ float wred[4][4];

    const int tid = threadIdx.x;
    const int b   = blockIdx.x;
    const float* pb = p + (size_t)b * N * DIM;
    const float* qb = q + (size_t)b * DIM;

    for (int k = tid; k < DIM; k += 128) qs[k] = qb[k];
    if (tid < N) lab_in[tid] = labels_g[b * N + tid];
    if (tid == 0) s_kmask = 0;
    __syncthreads();
    if (tid < N) atomicOr(&s_kmask, 1 << lab_in[tid]);

    // ---- Gram: G = S S^T, S = q ⊙ P.  128 thr = 16(ti) x 8(tj); tile 4x8 ----
    const int ti = tid >> 3, tj = tid & 7;
    const int i0 = ti * 4, j0 = tj * 8;

    unsigned long long acc[4][4];                     // acc[r][cp] packs cols (j0+2cp, j0+2cp+1)
    #pragma unroll
    for (int r = 0; r < 4; r++)
        #pragma unroll
        for (int cp = 0; cp < 4; cp++) acc[r][cp] = 0ull;

    for (int ch = 0; ch < NCHUNK; ch++) {
        __syncthreads();
        // fill ST k-major with swizzle: logical (k,i) -> ST[k][ ((i>>2 ^ (k>>2)&15)<<2) + (i&3) ]
        #pragma unroll
        for (int e = 0; e < 8; e++) {
            int idx = tid + e * 128;
            int row = idx >> 4;
            int kvb = idx & 15;            // = (k>>2) for the 4 k's this thread writes
            int kv  = kvb * 4;
            float4 v  = *reinterpret_cast<const float4*>(pb + row * DIM + ch * CHUNK + kv);
            const float4 qv = *reinterpret_cast<const float4*>(&qs[ch * CHUNK + kv]);
            v.x *= qv.x; v.y *= qv.y; v.z *= qv.z; v.w *= qv.w;
            int col = (((row >> 2) ^ kvb) << 2) + (row & 3);
            ST[kv + 0][col] = v.x;
            ST[kv + 1][col] = v.y;
            ST[kv + 2][col] = v.z;
            ST[kv + 3][col] = v.w;
        }
        __syncthreads();

        #pragma unroll
        for (int k4 = 0; k4 < 16; k4++) {
            const int avc  = ((ti ^ k4) << 2);
            const int bvc0 = (((2 * tj)     ^ k4) << 2);
            const int bvc1 = (((2 * tj + 1) ^ k4) << 2);
            #pragma unroll
            for (int t = 0; t < 4; t++) {
                const int kk = k4 * 4 + t;
                float4 av = *reinterpret_cast<const float4*>(&ST[kk][avc]);
                F4U B0, B1;
                B0.f = *reinterpret_cast<const float4*>(&ST[kk][bvc0]);
                B1.f = *reinterpret_cast<const float4*>(&ST[kk][bvc1]);
                unsigned long long a0, a1, a2, a3;
                asm("mov.b64 %0, {%1,%1};" : "=l"(a0) : "f"(av.x));
                asm("mov.b64 %0, {%1,%1};" : "=l"(a1) : "f"(av.y));
                asm("mov.b64 %0, {%1,%1};" : "=l"(a2) : "f"(av.z));
                asm("mov.b64 %0, {%1,%1};" : "=l"(a3) : "f"(av.w));
                #pragma unroll
                for (int cp = 0; cp < 4; cp++) {
                    unsigned long long bq = (cp < 2) ? B0.u[cp] : B1.u[cp - 2];
                    asm("fma.rn.f32x2 %0, %1, %2, %0;" : "+l"(acc[0][cp]) : "l"(a0), "l"(bq));
                    asm("fma.rn.f32x2 %0, %1, %2, %0;" : "+l"(acc[1][cp]) : "l"(a1), "l"(bq));
                    asm("fma.rn.f32x2 %0, %1, %2, %0;" : "+l"(acc[2][cp]) : "l"(a2), "l"(bq));
                    asm("fma.rn.f32x2 %0, %1, %2, %0;" : "+l"(acc[3][cp]) : "l"(a3), "l"(bq));
                }
            }
        }
    }

    // unpack accumulators
    float af[4][8];
    #pragma unroll
    for (int r = 0; r < 4; r++)
        #pragma unroll
        for (int cp = 0; cp < 4; cp++) {
            float lo, hi;
            asm("mov.b64 {%0,%1}, %2;" : "=f"(lo), "=f"(hi) : "l"(acc[r][cp]));
            af[r][2 * cp] = lo; af[r][2 * cp + 1] = hi;
        }

    __syncthreads();
    // diagonal (squared norms): the unique owner thread writes it
    #pragma unroll
    for (int r = 0; r < 4; r++) {
        int i = i0 + r;
        if (i >= j0 && i < j0 + 8) sqv[i] = af[r][i - j0];
    }
    __syncthreads();

    // ---- distances + similar/dissimilar partial sums ----
    float simN = 0.f, disN = 0.f, simC = 0.f;
    #pragma unroll
    for (int r = 0; r < 4; r++) {
        int i = i0 + r;
        int li = lab_in[i];
        #pragma unroll
        for (int c = 0; c < 8; c++) {
            int j = j0 + c;
            float d2 = sqv[i] + sqv[j] - 2.f * af[r][c];
            float dist = (d2 > 0.f) ? sqrtf(d2) : 0.f;
            D[i][j] = dist;
            if (li == lab_in[j]) { simN += dist; simC += 1.f; }
            else                 { disN += dist; }
        }
    }
    __syncthreads();
    if (tid < N) D[tid][tid] = BIGV;
    __syncthreads();

    // ---- initial row-min keys: 2 threads per row, 32 cols each ----
    {
        int row = tid >> 1, part = tid & 1;
        unsigned long long key = KINF;
        #pragma unroll
        for (int f = 0; f < 8; f++) {
            int c = part * 32 + f * 4;
            float4 v = *reinterpret_cast<const float4*>(&D[row][c]);
            key = u64min(key, packkey(v.x, row * 64 + c + 0));
            key = u64min(key, packkey(v.y, row * 64 + c + 1));
            key = u64min(key, packkey(v.z, row * 64 + c + 2));
            key = u64min(key, packkey(v.w, row * 64 + c + 3));
        }
        key = u64min(key, __shfl_down_sync(0xFFFFFFFFu, key, 1));
        if (part == 0) rowkey_sm[row] = key;
    }
    __syncthreads();

    const int merges = N - __popc(s_kmask);

    // ---- single-linkage: warp 0 only, warp-synchronous, O(n) per merge ----
    if (tid < 32) {
        const int lane = tid;
        const int c0 = 2 * lane, c1 = c0 + 1;
        unsigned long long rk0 = rowkey_sm[c0], rk1 = rowkey_sm[c1];
        unsigned long long pend = KINF;
        unsigned long long act = ~0ull;
        int aprev = -1;
        int lab0 = c0, lab1 = c1;

        for (int m = 0; m < merges; m++) {
            unsigned long long cand = u64min(u64min(rk0, rk1), pend);
            unsigned long long pr = pend;
            #pragma unroll
            for (int off = 16; off; off >>= 1) {
                cand = u64min(cand, __shfl_xor_sync(0xFFFFFFFFu, cand, off));
                pr   = u64min(pr,   __shfl_xor_sync(0xFFFFFFFFu, pr, off));
            }
            // materialize deferred rowkey of previous merge's row a
            if (aprev >= 0 && lane == (aprev >> 1)) {
                if (aprev & 1) rk1 = pr; else rk0 = pr;
            }
            int flat = (int)(cand & 0xFFFFFFFFull);
            int a = flat >> 6, bb = flat & 63;     // a < bb by flat-index minimality

            act &= ~(1ull << bb);

            // newrow = min(row a, row b); write row a and column a (mirrors reference)
            float m0 = fminf(D[a][c0], D[bb][c0]);
            float m1 = fminf(D[a][c1], D[bb][c1]);
            D[a][c0] = m0; D[a][c1] = m1;
            D[c0][a] = m0; D[c1][a] = m1;

            // deferred rowmin partial for row a (exclude diag + inactive)
            unsigned long long k0 = (((act >> c0) & 1ull) && c0 != a) ? packkey(m0, a * 64 + c0) : KINF;
            unsigned long long k1 = (((act >> c1) & 1ull) && c1 != a) ? packkey(m1, a * 64 + c1) : KINF;
            pend = u64min(k0, k1);
            aprev = a;

            // rowkey maintenance for this lane's two rows
            if (c0 == a || c0 == bb) rk0 = KINF;
            else if ((act >> c0) & 1ull) {
                if ((int)(rk0 & 63ull) == bb) rk0 = (rk0 & ~63ull) | (unsigned)a;  // redirect b->a
                rk0 = u64min(rk0, packkey(m0, c0 * 64 + a));
            }
            if (c1 == a || c1 == bb) rk1 = KINF;
            else if ((act >> c1) & 1ull) {
                if ((int)(rk1 & 63ull) == bb) rk1 = (rk1 & ~63ull) | (unsigned)a;
                rk1 = u64min(rk1, packkey(m1, c1 * 64 + a));
            }

            if (lab0 == bb) lab0 = a;
            if (lab1 == bb) lab1 = a;
            __syncwarp();
        }
        lab_sh[c0] = lab0;
        lab_sh[c1] = lab1;
    }
    __syncthreads();

    // ---- error count over this thread's 4x8 tile ----
    float errC = 0.f;
    #pragma unroll
    for (int r = 0; r < 4; r++) {
        int i = i0 + r;
        int ci = lab_sh[i], li = lab_in[i];
        #pragma unroll
        for (int c = 0; c < 8; c++) {
            int j = j0 + c;
            bool adj = (ci == lab_sh[j]);
            bool tru = (li == lab_in[j]);
            if (adj != tru) errC += 1.f;
        }
    }

    // ---- block reduce (4 warps) ----
    float v0 = simN, v1 = disN, v2 = simC, v3 = errC;
    #pragma unroll
    for (int o = 16; o > 0; o >>= 1) {
        v0 += __shfl_down_sync(0xFFFFFFFFu, v0, o);
        v1 += __shfl_down_sync(0xFFFFFFFFu, v1, o);
        v2 += __shfl_down_sync(0xFFFFFFFFu, v2, o);
        v3 += __shfl_down_sync(0xFFFFFFFFu, v3, o);
    }
    if ((tid & 31) == 0) {
        int w = tid >> 5;
        wred[w][0] = v0; wred[w][1] = v1; wred[w][2] = v2; wred[w][3] = v3;
    }
    __syncthreads();
    if (tid == 0) {
        float a0 = 0.f, a1 = 0.f, a2 = 0.f, a3 = 0.f;
        #pragma unroll
        for (int w = 0; w < 4; w++) {
            a0 += wred[w][0]; a1 += wred[w][1]; a2 += wred[w][2]; a3 += wred[w][3];
        }
        g_partials[b * 4 + 0] = a0;
        g_partials[b * 4 + 1] = a1;
        g_partials[b * 4 + 2] = a2;
        g_partials[b * 4 + 3] = a3;
    }
}

__global__ __launch_bounds__(256) void finalize_kernel(float* __restrict__ out)
{
    __shared__ double sh[8][4];
    const int tid = threadIdx.x;
    double v0 = g_partials[tid * 4 + 0];
    double v1 = g_partials[tid * 4 + 1];
    double v2 = g_partials[tid * 4 + 2];
    double v3 = g_partials[tid * 4 + 3];
    #pragma unroll
    for (int o = 16; o > 0; o >>= 1) {
        v0 += __shfl_down_sync(0xFFFFFFFFu, v0, o);
        v1 += __shfl_down_sync(0xFFFFFFFFu, v1, o);
        v2 += __shfl_down_sync(0xFFFFFFFFu, v2, o);
        v3 += __shfl_down_sync(0xFFFFFFFFu, v3, o);
    }
    if ((tid & 31) == 0) {
        int w = tid >> 5;
        sh[w][0] = v0; sh[w][1] = v1; sh[w][2] = v2; sh[w][3] = v3;
    }
    __syncthreads();
    if (tid == 0) {
        double simN = 0.0, disN = 0.0, simC = 0.0, errC = 0.0;
        #pragma unroll
        for (int w = 0; w < 8; w++) {
            simN += sh[w][0]; disN += sh[w][1]; simC += sh[w][2]; errC += sh[w][3];
        }
        double disC = (double)BATCH * N * N - simC;
        double res = errC / (double)BATCH + 0.5 * (simN / simC - disN / disC);
        out[0] = (float)res;
    }
}

extern "C" void kernel_launch(void* const* d_in, const int* in_sizes, int n_in,
                              void* d_out, int out_size)
{
    const float* q   = (const float*)d_in[0];  // [256, 768]
    const float* p   = (const float*)d_in[1];  // [256, 64, 768]
    const int*   lab = (const int*)d_in[2];    // [256, 64]
    (void)in_sizes; (void)n_in; (void)out_size;

    cluster_kernel<<<BATCH, 128>>>(q, p, lab);
    finalize_kernel<<<1, 256>>>((float*)d_out);
}